// round 2
// baseline (speedup 1.0000x reference)
#include <cuda_runtime.h>
#include <cuda_bf16.h>
#include <math.h>

// Levels: RES = {128, 256, 512, 1024}, C=4 channels, 3 planes per level.
// Transposed plane scratch layout per level: [p][y][x][c] (c fastest, float4 per texel).
#define NLEV 4

// sizes (floats): 3*4*R*R -> 196608, 786432, 3145728, 12582912 ; total 16711680 (~64MB)
__device__ __align__(16) float g_planes[16711680];
__device__ __align__(16) float g_linec[48];  // [l][p][c]

// ---------------------------------------------------------------------------
// Transpose: (3, C, R, R) -> (3, R, R, C) as float4 texels into g_planes+off
// ---------------------------------------------------------------------------
__global__ void transpose_kernel(const float* __restrict__ in, int off4, int R) {
    int i = blockIdx.x * blockDim.x + threadIdx.x;   // over 3*R*R texels
    int rr = R * R;
    int total = 3 * rr;
    if (i >= total) return;
    int p  = i / rr;
    int yx = i - p * rr;
    const float* src = in + (p * 4) * rr + yx;       // channel stride = R*R
    float4 v;
    v.x = src[0];
    v.y = src[rr];
    v.z = src[2 * rr];
    v.w = src[3 * rr];
    reinterpret_cast<float4*>(g_planes)[off4 + i] = v;
}

// ---------------------------------------------------------------------------
// Line constants: triline grid_sample degenerates to
//   linec[l,p,c] = 0.5*(tl[p,c,R/2-1,0] + tl[p,c,R/2,0])
// (width factor 1-0.5|coord| applied per point in the main kernel)
// ---------------------------------------------------------------------------
__global__ void linec_kernel(const float* __restrict__ t0, const float* __restrict__ t1,
                             const float* __restrict__ t2, const float* __restrict__ t3) {
    int i = threadIdx.x;
    if (i >= 48) return;
    const int res[NLEV] = {128, 256, 512, 1024};
    int l  = i / 12;
    int pc = i % 12;            // p*4 + c
    const float* t = (l == 0) ? t0 : (l == 1) ? t1 : (l == 2) ? t2 : t3;
    int r = res[l];
    // triline layout (3, C, r, 1): element [p][c][row] at pc*r + row
    g_linec[i] = 0.5f * (t[pc * r + r / 2 - 1] + t[pc * r + r / 2]);
}

// ---------------------------------------------------------------------------
// Main encoding kernel
// ---------------------------------------------------------------------------
__device__ __forceinline__ float4 sample_plane(const float4* __restrict__ b4,
                                               int R, float u, float v) {
    float fx = (u + 1.0f) * (0.5f * (float)R) - 0.5f;
    float fy = (v + 1.0f) * (0.5f * (float)R) - 0.5f;
    float fx0 = floorf(fx), fy0 = floorf(fy);
    float wx = fx - fx0, wy = fy - fy0;
    int x0 = (int)fx0, y0 = (int)fy0;
    int x1 = x0 + 1,   y1 = y0 + 1;
    bool vx0 = (x0 >= 0) && (x0 < R);
    bool vx1 = (x1 >= 0) && (x1 < R);
    bool vy0 = (y0 >= 0) && (y0 < R);
    bool vy1 = (y1 >= 0) && (y1 < R);
    float4 z = make_float4(0.f, 0.f, 0.f, 0.f);
    float4 v00 = (vx0 && vy0) ? __ldg(&b4[y0 * R + x0]) : z;
    float4 v10 = (vx1 && vy0) ? __ldg(&b4[y0 * R + x1]) : z;
    float4 v01 = (vx0 && vy1) ? __ldg(&b4[y1 * R + x0]) : z;
    float4 v11 = (vx1 && vy1) ? __ldg(&b4[y1 * R + x1]) : z;
    float w00 = (1.f - wx) * (1.f - wy);
    float w10 = wx * (1.f - wy);
    float w01 = (1.f - wx) * wy;
    float w11 = wx * wy;
    float4 acc;
    acc.x = v00.x * w00 + v10.x * w10 + v01.x * w01 + v11.x * w11;
    acc.y = v00.y * w00 + v10.y * w10 + v01.y * w01 + v11.y * w11;
    acc.z = v00.z * w00 + v10.z * w10 + v01.z * w01 + v11.z * w11;
    acc.w = v00.w * w00 + v10.w * w10 + v01.w * w01 + v11.w * w11;
    return acc;
}

__global__ __launch_bounds__(256)
void enc_kernel(const float* __restrict__ x, float* __restrict__ out, int N) {
    const int res[NLEV]  = {128, 256, 512, 1024};
    const int offs[NLEV] = {0, 196608, 983040, 4128768};  // floats

    int n = blockIdx.x * blockDim.x + threadIdx.x;
    if (n >= N) return;

    float px = 2.0f * x[3 * n + 0] - 1.0f;
    float py = 2.0f * x[3 * n + 1] - 1.0f;
    float pz = 2.0f * x[3 * n + 2] - 1.0f;

    // plane p: (u=width, v=height) per reference projections (xz), (yx), (zy)
    float uu[3] = {px, py, pz};
    float vv[3] = {pz, px, py};
    // line width factor per axis: 1 - 0.5*|coord|
    float wl[3] = {1.0f - 0.5f * fabsf(px),
                   1.0f - 0.5f * fabsf(py),
                   1.0f - 0.5f * fabsf(pz)};

    float4* o4 = reinterpret_cast<float4*>(out + (size_t)n * 48);
    const float4* lc4 = reinterpret_cast<const float4*>(g_linec);

#pragma unroll
    for (int l = 0; l < NLEV; l++) {
        const int R = res[l];
        const float4* lbase = reinterpret_cast<const float4*>(g_planes + offs[l]);
#pragma unroll
        for (int p = 0; p < 3; p++) {
            const float4* b4 = lbase + p * R * R;
            float4 acc = sample_plane(b4, R, uu[p], vv[p]);
            float4 lc = lc4[l * 3 + p];
            float s = wl[p];
            float4 r;
            r.x = acc.x * lc.x * s;
            r.y = acc.y * lc.y * s;
            r.z = acc.z * lc.z * s;
            r.w = acc.w * lc.w * s;
            o4[l * 3 + p] = r;
        }
    }
}

// ---------------------------------------------------------------------------
// Launch: identify inputs by size (robust to metadata ordering)
// ---------------------------------------------------------------------------
extern "C" void kernel_launch(void* const* d_in, const int* in_sizes, int n_in,
                              void* d_out, int out_size) {
    const int res[NLEV]  = {128, 256, 512, 1024};
    const int offs[NLEV] = {0, 196608, 983040, 4128768};  // floats

    // Expected sizes
    // triplane_l : 12*R*R = 196608, 786432, 3145728, 12582912
    // triline_l  : 12*R   = 1536, 3072, 6144, 12288
    // x          : 3*N    = 3145728 (ambiguous with triplane_2)
    int tp_idx[NLEV] = {-1, -1, -1, -1};
    int tl_idx[NLEV] = {-1, -1, -1, -1};
    int amb[2]; int n_amb = 0;   // indices with size 3145728
    int x_idx = -1;

    for (int i = 0; i < n_in; i++) {
        int s = in_sizes[i];
        if      (s == 196608)   tp_idx[0] = i;
        else if (s == 786432)   tp_idx[1] = i;
        else if (s == 12582912) tp_idx[3] = i;
        else if (s == 1536)     tl_idx[0] = i;
        else if (s == 3072)     tl_idx[1] = i;
        else if (s == 6144)     tl_idx[2] = i;
        else if (s == 12288)    tl_idx[3] = i;
        else if (s == 3145728)  { if (n_amb < 2) amb[n_amb++] = i; }
        else if (x_idx < 0)     x_idx = i;   // any other size: must be x
    }
    if (n_amb == 1) {
        // x has a different size; the single 3145728 entry is triplane_2
        tp_idx[2] = amb[0];
    } else if (n_amb == 2) {
        // triplane_0..3 are contiguous ascending in either metadata ordering:
        // the candidate strictly between tp1 and tp3 indices is triplane_2.
        int a = amb[0], b = amb[1];
        if (a > tp_idx[1] && a < tp_idx[3]) { tp_idx[2] = a; x_idx = b; }
        else                                { tp_idx[2] = b; x_idx = a; }
    }
    if (x_idx < 0) x_idx = 0;  // fallback

    const float* x = (const float*)d_in[x_idx];
    int N = in_sizes[x_idx] / 3;

    // 1) transpose plane tables into channel-interleaved layout
    for (int l = 0; l < NLEV; l++) {
        const float* tp = (const float*)d_in[tp_idx[l]];
        int total = 3 * res[l] * res[l];
        transpose_kernel<<<(total + 255) / 256, 256>>>(tp, offs[l] / 4, res[l]);
    }

    // 2) precompute line constants
    linec_kernel<<<1, 64>>>((const float*)d_in[tl_idx[0]], (const float*)d_in[tl_idx[1]],
                            (const float*)d_in[tl_idx[2]], (const float*)d_in[tl_idx[3]]);

    // 3) main pass
    enc_kernel<<<(N + 255) / 256, 256>>>(x, (float*)d_out, N);
}

// round 5
// speedup vs baseline: 1.6270x; 1.6270x over previous
#include <cuda_runtime.h>
#include <cuda_fp16.h>
#include <math.h>

// Levels: RES = {128, 256, 512, 1024}, C=4 channels, 3 planes per level.
//
// Plane storage: fp16 "pair table" per (level, plane):
//   P[ye][s] (16 bytes) = { texel(y=ye-1, x=s-1) c0..c3,  texel(y=ye-1, x=s) c0..c3 }
//   ye in [0, R+1], s in [0, R]; rows ye=0 / ye=R+1 and OOB columns are zeros.
// A bilinear sample at (x0,y0) = two aligned 16B loads: P[y0+1][x0+1], P[y0+2][x0+1].
#define NLEV 4

// texel counts per level: 3*(R+2)*(R+1) -> 50310, 198918, 791046, 3154950 ; total 4195224 (~67MB)
__device__ __align__(16) uint4 g_pairs[4195224];
__device__ __align__(16) float g_linec[48];  // [l][p][c]

__constant__ int   c_lvloff[NLEV]   = {0, 50310, 249228, 1040274};       // texel offsets
__constant__ int   c_pstride[NLEV]  = {16770, 66306, 263682, 1051650};   // (R+2)*(R+1)
__constant__ int   c_rowpitch[NLEV] = {129, 257, 513, 1025};             // R+1
__constant__ float c_halfR[NLEV]    = {64.f, 128.f, 256.f, 512.f};

// bit-reinterpret helpers (no-op in SASS)
__device__ __forceinline__ unsigned int h2_as_u32(__half2 h) {
    return *reinterpret_cast<unsigned int*>(&h);
}
__device__ __forceinline__ __half2 u32_as_h2(unsigned int u) {
    return *reinterpret_cast<__half2*>(&u);
}

// ---------------------------------------------------------------------------
// Build fp16 pair table with zero borders.
// grid: ( ceil((R+1)/256), R+2, 3 ) ; thread.x = s, block.y = ye, block.z = p
// ---------------------------------------------------------------------------
__global__ void transpose_kernel(const float* __restrict__ in, int R, int lvloff) {
    int s  = blockIdx.x * blockDim.x + threadIdx.x;      // 0..R
    if (s > R) return;
    int ye = blockIdx.y;                                 // 0..R+1
    int p  = blockIdx.z;
    int y  = ye - 1;
    int rr = R * R;
    bool yok = (y >= 0) && (y < R);
    bool lok = yok && (s >= 1);
    bool hok = yok && (s < R);
    const float* bp = in + (size_t)(p * 4) * rr + (size_t)y * R;

    __half h[8];
#pragma unroll
    for (int c = 0; c < 4; c++) {
        float lv = lok ? __ldg(bp + (size_t)c * rr + (s - 1)) : 0.f;
        float hv = hok ? __ldg(bp + (size_t)c * rr + s)       : 0.f;
        h[c]     = __float2half_rn(lv);
        h[4 + c] = __float2half_rn(hv);
    }
    uint4 t;
    t.x = h2_as_u32(__halves2half2(h[0], h[1]));   // lo texel c0,c1
    t.y = h2_as_u32(__halves2half2(h[2], h[3]));   // lo texel c2,c3
    t.z = h2_as_u32(__halves2half2(h[4], h[5]));   // hi texel c0,c1
    t.w = h2_as_u32(__halves2half2(h[6], h[7]));   // hi texel c2,c3
    int rp = R + 1;
    g_pairs[lvloff + p * (R + 2) * rp + ye * rp + s] = t;
}

// ---------------------------------------------------------------------------
// Line constants: triline grid_sample degenerates to
//   linec[l,p,c] = 0.5*(tl[p,c,R/2-1,0] + tl[p,c,R/2,0])
// (the width factor 1-0.5*|coord| is applied per point in the main kernel)
// ---------------------------------------------------------------------------
__global__ void linec_kernel(const float* __restrict__ t0, const float* __restrict__ t1,
                             const float* __restrict__ t2, const float* __restrict__ t3) {
    int i = threadIdx.x;
    if (i >= 48) return;
    const int res[NLEV] = {128, 256, 512, 1024};
    int l  = i / 12;
    int pc = i % 12;            // p*4 + c
    const float* t = (l == 0) ? t0 : (l == 1) ? t1 : (l == 2) ? t2 : t3;
    int r = res[l];
    g_linec[i] = 0.5f * (t[pc * r + r / 2 - 1] + t[pc * r + r / 2]);
}

// ---------------------------------------------------------------------------
// Main kernel: one thread per (point, level); 3 plane samples per thread.
// Writes 3 consecutive float4 -> warp output region is contiguous (coalesced).
// ---------------------------------------------------------------------------
__global__ __launch_bounds__(256)
void enc_kernel(const float* __restrict__ x, float* __restrict__ out, int N) {
    int tid   = blockIdx.x * blockDim.x + threadIdx.x;
    int point = tid >> 2;
    if (point >= N) return;
    int l = tid & 3;

    const float* xp = x + 3 * (size_t)point;
    float px = fmaf(2.f, __ldg(xp + 0), -1.f);
    float py = fmaf(2.f, __ldg(xp + 1), -1.f);
    float pz = fmaf(2.f, __ldg(xp + 2), -1.f);

    // plane p: (u=width, v=height) per reference projections (xz), (yx), (zy)
    float uu[3] = {px, py, pz};
    float vv[3] = {pz, px, py};
    float wl[3] = {fmaf(-0.5f, fabsf(px), 1.f),
                   fmaf(-0.5f, fabsf(py), 1.f),
                   fmaf(-0.5f, fabsf(pz), 1.f)};

    float hR   = c_halfR[l];
    int   rp   = c_rowpitch[l];
    int   base = c_lvloff[l];
    int   pstr = c_pstride[l];

    const float4* lc4 = reinterpret_cast<const float4*>(g_linec) + l * 3;
    float4* o4 = reinterpret_cast<float4*>(out) + (size_t)point * 12 + l * 3;

#pragma unroll
    for (int p = 0; p < 3; p++) {
        float fx = fmaf(uu[p], hR, hR - 0.5f);
        float fy = fmaf(vv[p], hR, hR - 0.5f);
        float fx0 = floorf(fx), fy0 = floorf(fy);
        float wx = fx - fx0,   wy = fy - fy0;
        int ix = (int)fx0, iy = (int)fy0;

        int idx = base + p * pstr + (iy + 1) * rp + (ix + 1);
        uint4 t0 = __ldg(&g_pairs[idx]);        // row y0: lo/hi texels
        uint4 t1 = __ldg(&g_pairs[idx + rp]);   // row y1

        __half2 wx2 = __float2half2_rn(wx);
        __half2 wy2 = __float2half2_rn(wy);

        __half2 a01 = u32_as_h2(t0.x), a23 = u32_as_h2(t0.y);
        __half2 b01 = u32_as_h2(t0.z), b23 = u32_as_h2(t0.w);
        __half2 c01 = u32_as_h2(t1.x), c23 = u32_as_h2(t1.y);
        __half2 d01 = u32_as_h2(t1.z), d23 = u32_as_h2(t1.w);

        // x-lerp both rows, then y-lerp (fp16)
        __half2 r01 = __hfma2(__hsub2(b01, a01), wx2, a01);
        __half2 r23 = __hfma2(__hsub2(b23, a23), wx2, a23);
        __half2 s01 = __hfma2(__hsub2(d01, c01), wx2, c01);
        __half2 s23 = __hfma2(__hsub2(d23, c23), wx2, c23);
        __half2 v01 = __hfma2(__hsub2(s01, r01), wy2, r01);
        __half2 v23 = __hfma2(__hsub2(s23, r23), wy2, r23);

        float2 f01 = __half22float2(v01);
        float2 f23 = __half22float2(v23);

        float4 lc = __ldg(&lc4[p]);
        float s = wl[p];
        float4 r;
        r.x = f01.x * lc.x * s;
        r.y = f01.y * lc.y * s;
        r.z = f23.x * lc.z * s;
        r.w = f23.y * lc.w * s;
        o4[p] = r;
    }
}

// ---------------------------------------------------------------------------
// Launch: identify inputs by size (robust to metadata ordering)
// ---------------------------------------------------------------------------
extern "C" void kernel_launch(void* const* d_in, const int* in_sizes, int n_in,
                              void* d_out, int out_size) {
    const int res[NLEV]    = {128, 256, 512, 1024};
    const int lvloff[NLEV] = {0, 50310, 249228, 1040274};

    // triplane_l : 12*R*R = 196608, 786432, 3145728, 12582912
    // triline_l  : 12*R   = 1536, 3072, 6144, 12288
    // x          : 3*N    = 3145728 (ambiguous with triplane_2)
    int tp_idx[NLEV] = {-1, -1, -1, -1};
    int tl_idx[NLEV] = {-1, -1, -1, -1};
    int amb[2]; int n_amb = 0;
    int x_idx = -1;

    for (int i = 0; i < n_in; i++) {
        int s = in_sizes[i];
        if      (s == 196608)   tp_idx[0] = i;
        else if (s == 786432)   tp_idx[1] = i;
        else if (s == 12582912) tp_idx[3] = i;
        else if (s == 1536)     tl_idx[0] = i;
        else if (s == 3072)     tl_idx[1] = i;
        else if (s == 6144)     tl_idx[2] = i;
        else if (s == 12288)    tl_idx[3] = i;
        else if (s == 3145728)  { if (n_amb < 2) amb[n_amb++] = i; }
        else if (x_idx < 0)     x_idx = i;
    }
    if (n_amb == 1) {
        tp_idx[2] = amb[0];
    } else if (n_amb == 2) {
        // triplane_0..3 occupy contiguous ascending indices in either ordering
        int a = amb[0], b = amb[1];
        if (a > tp_idx[1] && a < tp_idx[3]) { tp_idx[2] = a; x_idx = b; }
        else                                { tp_idx[2] = b; x_idx = a; }
    }
    if (x_idx < 0) x_idx = 0;

    const float* x = (const float*)d_in[x_idx];
    int N = in_sizes[x_idx] / 3;

    // 1) build fp16 pair tables (zero-bordered)
    for (int l = 0; l < NLEV; l++) {
        const float* tp = (const float*)d_in[tp_idx[l]];
        int R = res[l];
        dim3 grid((R + 1 + 255) / 256, R + 2, 3);
        transpose_kernel<<<grid, 256>>>(tp, R, lvloff[l]);
    }

    // 2) precompute line constants
    linec_kernel<<<1, 64>>>((const float*)d_in[tl_idx[0]], (const float*)d_in[tl_idx[1]],
                            (const float*)d_in[tl_idx[2]], (const float*)d_in[tl_idx[3]]);

    // 3) main pass: 4 threads per point (one per level)
    long long threads = 4LL * N;
    enc_kernel<<<(int)((threads + 255) / 256), 256>>>(x, (float*)d_out, N);
}

// round 9
// speedup vs baseline: 1.7213x; 1.0580x over previous
#include <cuda_runtime.h>
#include <cuda_fp16.h>
#include <math.h>

// Levels: RES = {128, 256, 512, 1024}, C=4 channels, 3 planes per level.
//
// Plane storage: fp16 "quad table" per (level, plane), lc-prefolded:
//   Quad[y][s] (32 bytes, 32B-aligned) =
//     { t(y-1,s-1), t(y-1,s), t(y,s-1), t(y,s) }  (each texel 4ch fp16 = 8B)
//   with every texel pre-multiplied by linec[l][p][c]; OOB texels are zero.
//   y,s in [0,R].  A bilinear sample at (ix,iy) reads Quad[iy+1][ix+1]:
//   two consecutive LDG.128 hitting the SAME 32B sector.
#define NLEV 4

// quads per level: 3*(R+1)^2 -> 49923, 198147, 789507, 3151875 ; total 4189452 (~134MB)
__device__ __align__(32) uint4 g_quads[8378904];   // 2 uint4 per quad
__device__ __align__(16) float g_linec[48];        // [l][p][c]

__constant__ int   c_lvloff[NLEV]   = {0, 49923, 248070, 1037577};       // quad offsets
__constant__ int   c_pstride[NLEV]  = {16641, 66049, 263169, 1050625};   // (R+1)^2
__constant__ int   c_rowpitch[NLEV] = {129, 257, 513, 1025};             // R+1
__constant__ float c_halfR[NLEV]    = {64.f, 128.f, 256.f, 512.f};

// bit-reinterpret helpers (no-op in SASS)
__device__ __forceinline__ unsigned int h2_as_u32(__half2 h) {
    return *reinterpret_cast<unsigned int*>(&h);
}
__device__ __forceinline__ __half2 u32_as_h2(unsigned int u) {
    return *reinterpret_cast<__half2*>(&u);
}

// ---------------------------------------------------------------------------
// Line constants: triline grid_sample degenerates to
//   linec[l,p,c] = 0.5*(tl[p,c,R/2-1,0] + tl[p,c,R/2,0])
// (the width factor 1-0.5*|coord| is applied per point in the main kernel)
// Runs BEFORE the quad builders, which fold these into the tables.
// ---------------------------------------------------------------------------
__global__ void linec_kernel(const float* __restrict__ t0, const float* __restrict__ t1,
                             const float* __restrict__ t2, const float* __restrict__ t3) {
    int i = threadIdx.x;
    if (i >= 48) return;
    const int res[NLEV] = {128, 256, 512, 1024};
    int l  = i / 12;
    int pc = i % 12;            // p*4 + c
    const float* t = (l == 0) ? t0 : (l == 1) ? t1 : (l == 2) ? t2 : t3;
    int r = res[l];
    g_linec[i] = 0.5f * (t[pc * r + r / 2 - 1] + t[pc * r + r / 2]);
}

// ---------------------------------------------------------------------------
// Build fp16 quad table (zero borders, lc-prefolded).
// grid: ( ceil((R+1)/128), R+1, 3 ) ; thread.x = s, block.y = y, block.z = p
// ---------------------------------------------------------------------------
__global__ void quad_kernel(const float* __restrict__ in, int R, int lvl) {
    int s = blockIdx.x * blockDim.x + threadIdx.x;       // 0..R
    if (s > R) return;
    int y = blockIdx.y;                                  // 0..R  (covers rows y-1, y)
    int p = blockIdx.z;
    int rr = R * R;
    const float* bp = in + (size_t)(p * 4) * rr;
    const float* lc = g_linec + lvl * 12 + p * 4;

    int ylo = y - 1, yhi = y;
    int xlo = s - 1, xhi = s;
    bool ylok = (ylo >= 0);          // ylo in [-1, R-1] -> valid iff >=0
    bool yhok = (yhi < R);           // yhi in [0, R]    -> valid iff < R
    bool xlok = (xlo >= 0);
    bool xhok = (xhi < R);

    __half hv[16];
#pragma unroll
    for (int c = 0; c < 4; c++) {
        const float* cp = bp + (size_t)c * rr;
        float l_ = lc[c];
        float v00 = (ylok && xlok) ? __ldg(cp + ylo * R + xlo) : 0.f;  // (y-1, s-1)
        float v01 = (ylok && xhok) ? __ldg(cp + ylo * R + xhi) : 0.f;  // (y-1, s)
        float v10 = (yhok && xlok) ? __ldg(cp + yhi * R + xlo) : 0.f;  // (y,   s-1)
        float v11 = (yhok && xhok) ? __ldg(cp + yhi * R + xhi) : 0.f;  // (y,   s)
        hv[c]      = __float2half_rn(v00 * l_);
        hv[4 + c]  = __float2half_rn(v01 * l_);
        hv[8 + c]  = __float2half_rn(v10 * l_);
        hv[12 + c] = __float2half_rn(v11 * l_);
    }
    uint4 t0, t1;
    t0.x = h2_as_u32(__halves2half2(hv[0],  hv[1]));   // row y0, x0: c0,c1
    t0.y = h2_as_u32(__halves2half2(hv[2],  hv[3]));   // row y0, x0: c2,c3
    t0.z = h2_as_u32(__halves2half2(hv[4],  hv[5]));   // row y0, x1: c0,c1
    t0.w = h2_as_u32(__halves2half2(hv[6],  hv[7]));   // row y0, x1: c2,c3
    t1.x = h2_as_u32(__halves2half2(hv[8],  hv[9]));   // row y1, x0
    t1.y = h2_as_u32(__halves2half2(hv[10], hv[11]));
    t1.z = h2_as_u32(__halves2half2(hv[12], hv[13]));  // row y1, x1
    t1.w = h2_as_u32(__halves2half2(hv[14], hv[15]));

    int rp = R + 1;
    int qidx = c_lvloff[lvl] + p * rp * rp + y * rp + s;
    g_quads[2 * qidx]     = t0;
    g_quads[2 * qidx + 1] = t1;
}

// ---------------------------------------------------------------------------
// Main kernel: one thread per (point, level); 3 plane samples per thread.
// Writes 3 consecutive float4 -> warp output region is contiguous (coalesced).
// ---------------------------------------------------------------------------
__global__ __launch_bounds__(256)
void enc_kernel(const float* __restrict__ x, float* __restrict__ out, int N) {
    int tid   = blockIdx.x * blockDim.x + threadIdx.x;
    int point = tid >> 2;
    if (point >= N) return;
    int l = tid & 3;

    const float* xp = x + 3 * (size_t)point;
    float px = fmaf(2.f, __ldg(xp + 0), -1.f);
    float py = fmaf(2.f, __ldg(xp + 1), -1.f);
    float pz = fmaf(2.f, __ldg(xp + 2), -1.f);

    // plane p: (u=width, v=height) per reference projections (xz), (yx), (zy)
    float uu[3] = {px, py, pz};
    float vv[3] = {pz, px, py};
    float wl[3] = {fmaf(-0.5f, fabsf(px), 1.f),
                   fmaf(-0.5f, fabsf(py), 1.f),
                   fmaf(-0.5f, fabsf(pz), 1.f)};

    float hR   = c_halfR[l];
    int   rp   = c_rowpitch[l];
    int   base = c_lvloff[l];
    int   pstr = c_pstride[l];

    float4* o4 = reinterpret_cast<float4*>(out) + (size_t)point * 12 + l * 3;

#pragma unroll
    for (int p = 0; p < 3; p++) {
        float fx = fmaf(uu[p], hR, hR - 0.5f);
        float fy = fmaf(vv[p], hR, hR - 0.5f);
        float fx0 = floorf(fx), fy0 = floorf(fy);
        float wx = fx - fx0,   wy = fy - fy0;
        int ix = (int)fx0, iy = (int)fy0;

        int qidx = base + p * pstr + (iy + 1) * rp + (ix + 1);
        const uint4* q = &g_quads[2 * qidx];
        uint4 t0 = __ldg(q);        // row y0: (x0 c01,c23), (x1 c01,c23)  [same 32B sector]
        uint4 t1 = __ldg(q + 1);    // row y1

        __half2 wx2 = __float2half2_rn(wx);
        __half2 wy2 = __float2half2_rn(wy);

        __half2 a01 = u32_as_h2(t0.x), a23 = u32_as_h2(t0.y);   // y0,x0
        __half2 b01 = u32_as_h2(t0.z), b23 = u32_as_h2(t0.w);   // y0,x1
        __half2 c01 = u32_as_h2(t1.x), c23 = u32_as_h2(t1.y);   // y1,x0
        __half2 d01 = u32_as_h2(t1.z), d23 = u32_as_h2(t1.w);   // y1,x1

        // x-lerp both rows, then y-lerp (fp16); lc already folded into texels
        __half2 r01 = __hfma2(__hsub2(b01, a01), wx2, a01);
        __half2 r23 = __hfma2(__hsub2(b23, a23), wx2, a23);
        __half2 s01 = __hfma2(__hsub2(d01, c01), wx2, c01);
        __half2 s23 = __hfma2(__hsub2(d23, c23), wx2, c23);
        __half2 v01 = __hfma2(__hsub2(s01, r01), wy2, r01);
        __half2 v23 = __hfma2(__hsub2(s23, r23), wy2, r23);

        float2 f01 = __half22float2(v01);
        float2 f23 = __half22float2(v23);

        float s = wl[p];
        float4 r;
        r.x = f01.x * s;
        r.y = f01.y * s;
        r.z = f23.x * s;
        r.w = f23.y * s;
        o4[p] = r;
    }
}

// ---------------------------------------------------------------------------
// Launch: identify inputs by size (robust to metadata ordering)
// ---------------------------------------------------------------------------
extern "C" void kernel_launch(void* const* d_in, const int* in_sizes, int n_in,
                              void* d_out, int out_size) {
    const int res[NLEV] = {128, 256, 512, 1024};

    // triplane_l : 12*R*R = 196608, 786432, 3145728, 12582912
    // triline_l  : 12*R   = 1536, 3072, 6144, 12288
    // x          : 3*N    = 3145728 (ambiguous with triplane_2)
    int tp_idx[NLEV] = {-1, -1, -1, -1};
    int tl_idx[NLEV] = {-1, -1, -1, -1};
    int amb[2]; int n_amb = 0;
    int x_idx = -1;

    for (int i = 0; i < n_in; i++) {
        int s = in_sizes[i];
        if      (s == 196608)   tp_idx[0] = i;
        else if (s == 786432)   tp_idx[1] = i;
        else if (s == 12582912) tp_idx[3] = i;
        else if (s == 1536)     tl_idx[0] = i;
        else if (s == 3072)     tl_idx[1] = i;
        else if (s == 6144)     tl_idx[2] = i;
        else if (s == 12288)    tl_idx[3] = i;
        else if (s == 3145728)  { if (n_amb < 2) amb[n_amb++] = i; }
        else if (x_idx < 0)     x_idx = i;
    }
    if (n_amb == 1) {
        tp_idx[2] = amb[0];
    } else if (n_amb == 2) {
        // triplane_0..3 occupy contiguous ascending indices in either ordering
        int a = amb[0], b = amb[1];
        if (a > tp_idx[1] && a < tp_idx[3]) { tp_idx[2] = a; x_idx = b; }
        else                                { tp_idx[2] = b; x_idx = a; }
    }
    if (x_idx < 0) x_idx = 0;

    const float* x = (const float*)d_in[x_idx];
    int N = in_sizes[x_idx] / 3;

    // 1) line constants first (folded into quad tables)
    linec_kernel<<<1, 64>>>((const float*)d_in[tl_idx[0]], (const float*)d_in[tl_idx[1]],
                            (const float*)d_in[tl_idx[2]], (const float*)d_in[tl_idx[3]]);

    // 2) build fp16 quad tables (zero-bordered, lc-prefolded)
    for (int l = 0; l < NLEV; l++) {
        const float* tp = (const float*)d_in[tp_idx[l]];
        int R = res[l];
        dim3 grid((R + 1 + 127) / 128, R + 1, 3);
        quad_kernel<<<grid, 128>>>(tp, R, l);
    }

    // 3) main pass: 4 threads per point (one per level)
    long long threads = 4LL * N;
    enc_kernel<<<(int)((threads + 255) / 256), 256>>>(x, (float*)d_out, N);
}

// round 10
// speedup vs baseline: 1.7416x; 1.0118x over previous
#include <cuda_runtime.h>
#include <cuda_fp16.h>
#include <math.h>

// Levels: RES = {128, 256, 512, 1024}, C=4 channels, 3 planes per level.
//
// Plane storage: fp16 "quad table" per (level, plane), lc-prefolded:
//   Quad[y][s] (32 bytes, 32B-aligned) =
//     { t(y-1,s-1), t(y-1,s), t(y,s-1), t(y,s) }  (each texel 4ch fp16 = 8B)
//   with every texel pre-multiplied by linec[l][p][c]; OOB texels are zero.
//   y,s in [0,R].  A bilinear sample at (ix,iy) reads Quad[iy+1][ix+1].
// enc uses 8 threads/point: lane pairs split a quad's two rows so each
// warp-level LDG.128 touches only 16 distinct lines (halved L1tex wavefronts).
#define NLEV 4

// quads per level: 3*(R+1)^2 -> 49923, 198147, 789507, 3151875 ; total 4189452 (~134MB)
__device__ __align__(32) uint4 g_quads[8378904];   // 2 uint4 per quad
__device__ __align__(16) float g_linec[48];        // [l][p][c]

__constant__ int   c_lvloff[NLEV]   = {0, 49923, 248070, 1037577};       // quad offsets
__constant__ int   c_pstride[NLEV]  = {16641, 66049, 263169, 1050625};   // (R+1)^2

// per-sample (s = l*3+p) prefolded params
__constant__ int c_sbase[12] = {
    0, 16641, 33282,
    49923, 115972, 182021,
    248070, 511239, 774408,
    1037577, 2088202, 3138827};
__constant__ int c_srp[12] = {129,129,129, 257,257,257, 513,513,513, 1025,1025,1025};
__constant__ float c_shR[12] = {64.f,64.f,64.f, 128.f,128.f,128.f,
                                256.f,256.f,256.f, 512.f,512.f,512.f};
__constant__ int c_spn[12] = {0,1,2, 0,1,2, 0,1,2, 0,1,2};

// bit-reinterpret helpers (no-op in SASS)
__device__ __forceinline__ unsigned int h2_as_u32(__half2 h) {
    return *reinterpret_cast<unsigned int*>(&h);
}
__device__ __forceinline__ __half2 u32_as_h2(unsigned int u) {
    return *reinterpret_cast<__half2*>(&u);
}

// ---------------------------------------------------------------------------
// Line constants: triline grid_sample degenerates to
//   linec[l,p,c] = 0.5*(tl[p,c,R/2-1,0] + tl[p,c,R/2,0])
// Runs BEFORE the quad builders, which fold these into the tables.
// ---------------------------------------------------------------------------
__global__ void linec_kernel(const float* __restrict__ t0, const float* __restrict__ t1,
                             const float* __restrict__ t2, const float* __restrict__ t3) {
    int i = threadIdx.x;
    if (i >= 48) return;
    const int res[NLEV] = {128, 256, 512, 1024};
    int l  = i / 12;
    int pc = i % 12;            // p*4 + c
    const float* t = (l == 0) ? t0 : (l == 1) ? t1 : (l == 2) ? t2 : t3;
    int r = res[l];
    g_linec[i] = 0.5f * (t[pc * r + r / 2 - 1] + t[pc * r + r / 2]);
}

// ---------------------------------------------------------------------------
// Build fp16 quad table (zero borders, lc-prefolded).
// grid: ( ceil((R+1)/128), R+1, 3 ) ; thread.x = s, block.y = y, block.z = p
// ---------------------------------------------------------------------------
__global__ void quad_kernel(const float* __restrict__ in, int R, int lvl) {
    int s = blockIdx.x * blockDim.x + threadIdx.x;       // 0..R
    if (s > R) return;
    int y = blockIdx.y;                                  // 0..R  (covers rows y-1, y)
    int p = blockIdx.z;
    int rr = R * R;
    const float* bp = in + (size_t)(p * 4) * rr;
    const float* lc = g_linec + lvl * 12 + p * 4;

    int ylo = y - 1, yhi = y;
    int xlo = s - 1, xhi = s;
    bool ylok = (ylo >= 0);
    bool yhok = (yhi < R);
    bool xlok = (xlo >= 0);
    bool xhok = (xhi < R);

    __half hv[16];
#pragma unroll
    for (int c = 0; c < 4; c++) {
        const float* cp = bp + (size_t)c * rr;
        float l_ = lc[c];
        float v00 = (ylok && xlok) ? __ldg(cp + ylo * R + xlo) : 0.f;  // (y-1, s-1)
        float v01 = (ylok && xhok) ? __ldg(cp + ylo * R + xhi) : 0.f;  // (y-1, s)
        float v10 = (yhok && xlok) ? __ldg(cp + yhi * R + xlo) : 0.f;  // (y,   s-1)
        float v11 = (yhok && xhok) ? __ldg(cp + yhi * R + xhi) : 0.f;  // (y,   s)
        hv[c]      = __float2half_rn(v00 * l_);
        hv[4 + c]  = __float2half_rn(v01 * l_);
        hv[8 + c]  = __float2half_rn(v10 * l_);
        hv[12 + c] = __float2half_rn(v11 * l_);
    }
    uint4 t0, t1;
    t0.x = h2_as_u32(__halves2half2(hv[0],  hv[1]));
    t0.y = h2_as_u32(__halves2half2(hv[2],  hv[3]));
    t0.z = h2_as_u32(__halves2half2(hv[4],  hv[5]));
    t0.w = h2_as_u32(__halves2half2(hv[6],  hv[7]));
    t1.x = h2_as_u32(__halves2half2(hv[8],  hv[9]));
    t1.y = h2_as_u32(__halves2half2(hv[10], hv[11]));
    t1.z = h2_as_u32(__halves2half2(hv[12], hv[13]));
    t1.w = h2_as_u32(__halves2half2(hv[14], hv[15]));

    int rp = R + 1;
    int qidx = c_lvloff[lvl] + p * rp * rp + y * rp + s;
    g_quads[2 * qidx]     = t0;
    g_quads[2 * qidx + 1] = t1;
}

// ---------------------------------------------------------------------------
// Main kernel: 8 threads per point. Pair (2j, 2j+1) handles sample s = j+4r
// per round r=0..2; even lane loads quad row y0, odd lane row y1. After the
// per-row x-lerp, the rows are exchanged via shfl_xor(1); the even lane
// finalizes channels 0-1 and the odd lane channels 2-3 (8B store each).
// ---------------------------------------------------------------------------
__global__ __launch_bounds__(256)
void enc_kernel(const float* __restrict__ x, float* __restrict__ out, int N) {
    int tid   = blockIdx.x * blockDim.x + threadIdx.x;
    int point = tid >> 3;
    bool live = (point < N);
    if (point >= N) point = N - 1;     // clamp: keep all lanes active for shfl
    int t   = tid & 7;
    int j   = t >> 1;                  // pair id 0..3
    int row = t & 1;                   // 0 = row y0, 1 = row y1

    const float* xp = x + 3 * (size_t)point;
    float px = fmaf(2.f, __ldg(xp + 0), -1.f);
    float py = fmaf(2.f, __ldg(xp + 1), -1.f);
    float pz = fmaf(2.f, __ldg(xp + 2), -1.f);

    float2* o2 = reinterpret_cast<float2*>(out + (size_t)point * 48);

#pragma unroll
    for (int r = 0; r < 3; r++) {
        int s = j + 4 * r;             // sample id 0..11

        int   base = c_sbase[s];
        int   rp   = c_srp[s];
        float hR   = c_shR[s];
        int   p    = c_spn[s];

        // plane p: (u=width, v=height) per projections (xz), (yx), (zy)
        float u  = (p == 0) ? px : (p == 1) ? py : pz;
        float v  = (p == 0) ? pz : (p == 1) ? px : py;
        float wl = fmaf(-0.5f, fabsf(u), 1.f);   // line factor uses axis coord = u

        float fx = fmaf(u, hR, hR - 0.5f);
        float fy = fmaf(v, hR, hR - 0.5f);
        float fx0 = floorf(fx), fy0 = floorf(fy);
        float wx = fx - fx0,   wy = fy - fy0;
        int ix = (int)fx0, iy = (int)fy0;

        int qidx = base + (iy + 1) * rp + (ix + 1);
        uint4 tq = __ldg(&g_quads[2 * qidx + row]);   // my row: (x0 c01,c23),(x1 c01,c23)

        __half2 wx2 = __float2half2_rn(wx);
        __half2 a01 = u32_as_h2(tq.x), a23 = u32_as_h2(tq.y);   // x0
        __half2 b01 = u32_as_h2(tq.z), b23 = u32_as_h2(tq.w);   // x1

        // x-lerp my row
        __half2 r01 = __hfma2(__hsub2(b01, a01), wx2, a01);
        __half2 r23 = __hfma2(__hsub2(b23, a23), wx2, a23);

        // exchange with partner row
        unsigned o01 = __shfl_xor_sync(0xffffffffu, h2_as_u32(r01), 1);
        unsigned o23 = __shfl_xor_sync(0xffffffffu, h2_as_u32(r23), 1);

        // even lane (row 0): channels 0-1 -> lo = own r01 (y0), hi = partner (y1)
        // odd  lane (row 1): channels 2-3 -> lo = partner r23 (y0), hi = own (y1)
        __half2 lo = (row == 0) ? r01 : u32_as_h2(o23);
        __half2 hi = (row == 0) ? u32_as_h2(o01) : r23;

        __half2 wy2 = __float2half2_rn(wy);
        __half2 vv2 = __hfma2(__hsub2(hi, lo), wy2, lo);
        float2 f = __half22float2(vv2);

        float2 res;
        res.x = f.x * wl;
        res.y = f.y * wl;
        if (live) o2[s * 2 + row] = res;
    }
}

// ---------------------------------------------------------------------------
// Launch: identify inputs by size (robust to metadata ordering)
// ---------------------------------------------------------------------------
extern "C" void kernel_launch(void* const* d_in, const int* in_sizes, int n_in,
                              void* d_out, int out_size) {
    const int res[NLEV] = {128, 256, 512, 1024};

    // triplane_l : 12*R*R = 196608, 786432, 3145728, 12582912
    // triline_l  : 12*R   = 1536, 3072, 6144, 12288
    // x          : 3*N    = 3145728 (ambiguous with triplane_2)
    int tp_idx[NLEV] = {-1, -1, -1, -1};
    int tl_idx[NLEV] = {-1, -1, -1, -1};
    int amb[2]; int n_amb = 0;
    int x_idx = -1;

    for (int i = 0; i < n_in; i++) {
        int s = in_sizes[i];
        if      (s == 196608)   tp_idx[0] = i;
        else if (s == 786432)   tp_idx[1] = i;
        else if (s == 12582912) tp_idx[3] = i;
        else if (s == 1536)     tl_idx[0] = i;
        else if (s == 3072)     tl_idx[1] = i;
        else if (s == 6144)     tl_idx[2] = i;
        else if (s == 12288)    tl_idx[3] = i;
        else if (s == 3145728)  { if (n_amb < 2) amb[n_amb++] = i; }
        else if (x_idx < 0)     x_idx = i;
    }
    if (n_amb == 1) {
        tp_idx[2] = amb[0];
    } else if (n_amb == 2) {
        // triplane_0..3 occupy contiguous ascending indices in either ordering
        int a = amb[0], b = amb[1];
        if (a > tp_idx[1] && a < tp_idx[3]) { tp_idx[2] = a; x_idx = b; }
        else                                { tp_idx[2] = b; x_idx = a; }
    }
    if (x_idx < 0) x_idx = 0;

    const float* x = (const float*)d_in[x_idx];
    int N = in_sizes[x_idx] / 3;

    // 1) line constants first (folded into quad tables)
    linec_kernel<<<1, 64>>>((const float*)d_in[tl_idx[0]], (const float*)d_in[tl_idx[1]],
                            (const float*)d_in[tl_idx[2]], (const float*)d_in[tl_idx[3]]);

    // 2) build fp16 quad tables (zero-bordered, lc-prefolded)
    for (int l = 0; l < NLEV; l++) {
        const float* tp = (const float*)d_in[tp_idx[l]];
        int R = res[l];
        dim3 grid((R + 1 + 127) / 128, R + 1, 3);
        quad_kernel<<<grid, 128>>>(tp, R, l);
    }

    // 3) main pass: 8 threads per point (pair per sample slot)
    long long threads = 8LL * N;
    enc_kernel<<<(int)((threads + 255) / 256), 256>>>(x, (float*)d_out, N);
}